// round 1
// baseline (speedup 1.0000x reference)
#include <cuda_runtime.h>

// cosine_regularizer: out = (sum(W) - N)/N^2 with W = p p^T, p = row-normalized points.
// Identity: sum(W) = || sum_i p_i ||^2  -> single streaming pass over the input.

constexpr int N_ROWS = 16384;
constexpr int D      = 256;
constexpr int TPB    = 256;                 // 8 warps
constexpr int WARPS  = TPB / 32;
constexpr int NBLK   = 512;                 // 512*8 warps * 4 rows = 16384 rows
constexpr int ROWS_PER_WARP = N_ROWS / (NBLK * WARPS);  // 4

__device__ float g_s[D];   // zero-initialized at module load; k_final resets it each run

__global__ void __launch_bounds__(TPB)
k_main(const float* __restrict__ pts) {
    const int warp  = threadIdx.x >> 5;
    const int lane  = threadIdx.x & 31;
    const int gwarp = blockIdx.x * WARPS + warp;   // 0 .. NBLK*WARPS-1

    // Issue all loads for this warp's 4 rows up front (MLP).
    float4 v0[ROWS_PER_WARP], v1[ROWS_PER_WARP];
#pragma unroll
    for (int k = 0; k < ROWS_PER_WARP; k++) {
        const int row = gwarp + k * (NBLK * WARPS);
        const float4* p = reinterpret_cast<const float4*>(pts) + (size_t)row * (D / 4);
        v0[k] = p[lane];        // cols 4*lane .. 4*lane+3
        v1[k] = p[32 + lane];   // cols 128+4*lane .. 128+4*lane+3
    }

    // Per-row sum of squares, then warp-wide reduction (4 chains interleaved).
    float ss[ROWS_PER_WARP];
#pragma unroll
    for (int k = 0; k < ROWS_PER_WARP; k++) {
        ss[k] = v0[k].x * v0[k].x + v0[k].y * v0[k].y + v0[k].z * v0[k].z + v0[k].w * v0[k].w
              + v1[k].x * v1[k].x + v1[k].y * v1[k].y + v1[k].z * v1[k].z + v1[k].w * v1[k].w;
    }
#pragma unroll
    for (int off = 16; off > 0; off >>= 1) {
#pragma unroll
        for (int k = 0; k < ROWS_PER_WARP; k++)
            ss[k] += __shfl_xor_sync(0xffffffffu, ss[k], off);
    }

    // Accumulate rnorm * row into per-lane column accumulators.
    float4 a0 = make_float4(0.f, 0.f, 0.f, 0.f);
    float4 a1 = make_float4(0.f, 0.f, 0.f, 0.f);
#pragma unroll
    for (int k = 0; k < ROWS_PER_WARP; k++) {
        const float rn = rsqrtf(ss[k]);
        a0.x += rn * v0[k].x;  a0.y += rn * v0[k].y;
        a0.z += rn * v0[k].z;  a0.w += rn * v0[k].w;
        a1.x += rn * v1[k].x;  a1.y += rn * v1[k].y;
        a1.z += rn * v1[k].z;  a1.w += rn * v1[k].w;
    }

    // Block reduce 8 warps' column partials, one atomic per column per block.
    __shared__ float sh[WARPS][D];
    float4* shv = reinterpret_cast<float4*>(sh[warp]);
    shv[lane]      = a0;
    shv[32 + lane] = a1;
    __syncthreads();

    const int t = threadIdx.x;
    float s = sh[0][t];
#pragma unroll
    for (int w = 1; w < WARPS; w++) s += sh[w][t];
    atomicAdd(&g_s[t], s);
}

__global__ void __launch_bounds__(D)
k_final(float* __restrict__ out) {
    const int t = threadIdx.x;
    const float v = g_s[t];
    g_s[t] = 0.0f;   // reset for the next (graph-replayed) invocation

    __shared__ double sh[D];
    sh[t] = (double)v * (double)v;
    __syncthreads();
#pragma unroll
    for (int s = D / 2; s > 0; s >>= 1) {
        if (t < s) sh[t] += sh[t + s];
        __syncthreads();
    }
    if (t == 0) {
        const double n = (double)N_ROWS;
        out[0] = (float)((sh[0] - n) / (n * n));
    }
}

extern "C" void kernel_launch(void* const* d_in, const int* in_sizes, int n_in,
                              void* d_out, int out_size) {
    const float* pts = (const float*)d_in[0];
    (void)in_sizes; (void)n_in; (void)out_size;
    k_main<<<NBLK, TPB>>>(pts);
    k_final<<<1, D>>>((float*)d_out);
}